// round 4
// baseline (speedup 1.0000x reference)
#include <cuda_runtime.h>
#include <cuda_bf16.h>
#include <math.h>

// Problem dims
#define BB   32
#define NN   256
#define DIMD 384
#define HH   6
#define DHD  64
#define MLPD 1536
#define DEPTH 12
#define INNERD 384
#define BN_ROWS (BB*NN)          // 8192

// Scratch (device globals; allocation in kernel_launch is forbidden)
__device__ float g_x   [BN_ROWS*DIMD];
__device__ float g_y   [BN_ROWS*DIMD];
__device__ float g_q   [BN_ROWS*INNERD];
__device__ float g_kv  [BN_ROWS*2*INNERD];
__device__ float g_o   [BN_ROWS*INNERD];
__device__ float g_h   [BN_ROWS*MLPD];
__device__ float g_dots[BB*HH*NN*NN];
__device__ float g_attn[BB*HH*NN*NN];

// ---------------------------------------------------------------------------
// LayerNorm: one block (128 threads) per row of 384
// ---------------------------------------------------------------------------
__global__ __launch_bounds__(128) void ln_kernel(
    const float* __restrict__ x, const float* __restrict__ g,
    const float* __restrict__ b, float* __restrict__ y)
{
    int row = blockIdx.x;
    int t = threadIdx.x;               // 128
    const float* xr = x + (size_t)row * DIMD;
    float v0 = xr[t], v1 = xr[t + 128], v2 = xr[t + 256];

    __shared__ float scratch[4];
    float s = v0 + v1 + v2;
    #pragma unroll
    for (int o = 16; o; o >>= 1) s += __shfl_xor_sync(0xffffffffu, s, o);
    if ((t & 31) == 0) scratch[t >> 5] = s;
    __syncthreads();
    s = scratch[0] + scratch[1] + scratch[2] + scratch[3];
    float mean = s * (1.0f / DIMD);

    float d0 = v0 - mean, d1 = v1 - mean, d2 = v2 - mean;
    float q = d0 * d0 + d1 * d1 + d2 * d2;
    __syncthreads();
    #pragma unroll
    for (int o = 16; o; o >>= 1) q += __shfl_xor_sync(0xffffffffu, q, o);
    if ((t & 31) == 0) scratch[t >> 5] = q;
    __syncthreads();
    q = scratch[0] + scratch[1] + scratch[2] + scratch[3];
    float rstd = rsqrtf(q * (1.0f / DIMD) + 1e-5f);

    float* yr = y + (size_t)row * DIMD;
    yr[t]       = d0 * rstd * g[t]       + b[t];
    yr[t + 128] = d1 * rstd * g[t + 128] + b[t + 128];
    yr[t + 256] = d2 * rstd * g[t + 256] + b[t + 256];
}

// ---------------------------------------------------------------------------
// Dense SGEMM: C[M,N] = A[M,K] * W[K,N], row-major, M%64==0, N%64==0, K%16==0
// EPI 0: none; 1: gelu(c+bias); 2: (c+bias)*ls + res
// 256 threads, BM=BN=64, BK=16, 4x4 per thread
// ---------------------------------------------------------------------------
template<int EPI>
__global__ __launch_bounds__(256) void sgemm_kernel(
    const float* __restrict__ A, const float* __restrict__ W,
    float* __restrict__ C, int M, int K, int N,
    const float* __restrict__ bias,
    const float* __restrict__ ls,
    const float* __restrict__ res)
{
    __shared__ float As[16][68];   // transposed: As[k][m]
    __shared__ float Ws[16][64];
    int tid = threadIdx.x;
    int tx = tid & 15, ty = tid >> 4;
    int m0 = blockIdx.y * 64;
    int n0 = blockIdx.x * 64;
    float acc[4][4] = {};

    for (int k0 = 0; k0 < K; k0 += 16) {
        {   // A tile 64x16 -> 256 float4
            int row = tid >> 2;
            int vec = tid & 3;
            float4 a = *(const float4*)&A[(size_t)(m0 + row) * K + k0 + vec * 4];
            As[vec * 4 + 0][row] = a.x;
            As[vec * 4 + 1][row] = a.y;
            As[vec * 4 + 2][row] = a.z;
            As[vec * 4 + 3][row] = a.w;
        }
        {   // W tile 16x64 -> 256 float4
            int row = tid >> 4;
            int vec = tid & 15;
            *(float4*)&Ws[row][vec * 4] =
                *(const float4*)&W[(size_t)(k0 + row) * N + n0 + vec * 4];
        }
        __syncthreads();
        #pragma unroll
        for (int kk = 0; kk < 16; kk++) {
            float4 a4 = *(const float4*)&As[kk][ty * 4];
            float4 b4 = *(const float4*)&Ws[kk][tx * 4];
            float a[4] = {a4.x, a4.y, a4.z, a4.w};
            float bb[4] = {b4.x, b4.y, b4.z, b4.w};
            #pragma unroll
            for (int i = 0; i < 4; i++)
                #pragma unroll
                for (int j = 0; j < 4; j++)
                    acc[i][j] = fmaf(a[i], bb[j], acc[i][j]);
        }
        __syncthreads();
    }

    #pragma unroll
    for (int i = 0; i < 4; i++) {
        int m = m0 + ty * 4 + i;
        #pragma unroll
        for (int j = 0; j < 4; j++) {
            int n = n0 + tx * 4 + j;
            float c = acc[i][j];
            if (EPI == 1) {
                c += bias[n];
                c = 0.5f * c * (1.0f + erff(c * 0.70710678118654752f));
            } else if (EPI == 2) {
                c = (c + bias[n]) * ls[n] + res[(size_t)m * N + n];
            }
            C[(size_t)m * N + n] = c;
        }
    }
}

// ---------------------------------------------------------------------------
// dots[b,h,i,j] = scale[h] * sum_d q[b,i,h,d]*k[b,j,h,d]
// grid (4,4,B*H), 256 threads, 64x64 tile, K=64, 4x4 per thread
// ---------------------------------------------------------------------------
__global__ __launch_bounds__(256) void dots_kernel(
    const float* __restrict__ q, const float* __restrict__ kv,
    const float* __restrict__ scale, float* __restrict__ dots)
{
    int bh = blockIdx.z;
    int b = bh / HH, h = bh % HH;
    int i0 = blockIdx.y * 64, j0 = blockIdx.x * 64;
    __shared__ float Qs[64][65];
    __shared__ float Ks[64][65];
    int tid = threadIdx.x, tx = tid & 15, ty = tid >> 4;

    #pragma unroll
    for (int v = 0; v < 4; v++) {
        int lin = tid + v * 256;
        int r = lin >> 4, c = (lin & 15) * 4;
        float4 qa = *(const float4*)&q[(size_t)(b * NN + i0 + r) * INNERD + h * DHD + c];
        Qs[r][c] = qa.x; Qs[r][c + 1] = qa.y; Qs[r][c + 2] = qa.z; Qs[r][c + 3] = qa.w;
        float4 ka = *(const float4*)&kv[(size_t)(b * NN + j0 + r) * (2 * INNERD) + h * DHD + c];
        Ks[r][c] = ka.x; Ks[r][c + 1] = ka.y; Ks[r][c + 2] = ka.z; Ks[r][c + 3] = ka.w;
    }
    __syncthreads();

    float acc[4][4] = {};
    #pragma unroll 8
    for (int d = 0; d < 64; d++) {
        float a[4], bb[4];
        #pragma unroll
        for (int i = 0; i < 4; i++) a[i] = Qs[ty * 4 + i][d];
        #pragma unroll
        for (int j = 0; j < 4; j++) bb[j] = Ks[tx * 4 + j][d];
        #pragma unroll
        for (int i = 0; i < 4; i++)
            #pragma unroll
            for (int j = 0; j < 4; j++)
                acc[i][j] = fmaf(a[i], bb[j], acc[i][j]);
    }

    float sc = scale[h];
    #pragma unroll
    for (int i = 0; i < 4; i++)
        #pragma unroll
        for (int j = 0; j < 4; j++)
            dots[((size_t)bh * NN + i0 + ty * 4 + i) * NN + j0 + tx * 4 + j] = acc[i][j] * sc;
}

// ---------------------------------------------------------------------------
// Fused pre-mix -> diag mask -> softmax -> post-mix.
// One block per (b,i); 256 threads, thread = j; all 6 heads in registers.
// ---------------------------------------------------------------------------
__device__ __forceinline__ float block_reduce(float v, bool is_max, float* scratch)
{
    #pragma unroll
    for (int o = 16; o; o >>= 1) {
        float t = __shfl_xor_sync(0xffffffffu, v, o);
        v = is_max ? fmaxf(v, t) : v + t;
    }
    __syncthreads();
    if ((threadIdx.x & 31) == 0) scratch[threadIdx.x >> 5] = v;
    __syncthreads();
    float r = scratch[0];
    #pragma unroll
    for (int k = 1; k < 8; k++) r = is_max ? fmaxf(r, scratch[k]) : r + scratch[k];
    return r;
}

__global__ __launch_bounds__(256) void softmax_mix_kernel(
    const float* __restrict__ dots,
    const float* __restrict__ mp,
    const float* __restrict__ mq,
    float* __restrict__ attn)
{
    int b = blockIdx.x >> 8;
    int i = blockIdx.x & 255;
    int j = threadIdx.x;

    __shared__ float smp[36], smq[36], red[8];
    if (j < 36) { smp[j] = mp[j]; smq[j] = mq[j]; }

    float raw[HH];
    #pragma unroll
    for (int h = 0; h < HH; h++)
        raw[h] = dots[(((size_t)b * HH + h) * NN + i) * NN + j];
    __syncthreads();

    float pm[HH];
    #pragma unroll
    for (int g = 0; g < HH; g++) {
        float s = 0.0f;
        #pragma unroll
        for (int h = 0; h < HH; h++) s = fmaf(raw[h], smp[h * HH + g], s);
        pm[g] = s;
    }
    if (j == i) {
        #pragma unroll
        for (int g = 0; g < HH; g++) pm[g] = -INFINITY;
    }

    float a[HH];
    #pragma unroll
    for (int g = 0; g < HH; g++) {
        float m  = block_reduce(pm[g], true, red);
        float e  = expf(pm[g] - m);
        float s  = block_reduce(e, false, red);
        a[g] = e / s;
    }

    #pragma unroll
    for (int g = 0; g < HH; g++) {
        float s = 0.0f;
        #pragma unroll
        for (int h = 0; h < HH; h++) s = fmaf(a[h], smq[h * HH + g], s);
        attn[(((size_t)b * HH + g) * NN + i) * NN + j] = s;
    }
}

// ---------------------------------------------------------------------------
// o[b,i, h*64+d] = sum_j attn[b,h,i,j] * v[b,j,h,d]
// grid (4, B*H), 256 threads, 64(i)x64(d) tile, BK=32 over j
// ---------------------------------------------------------------------------
__global__ __launch_bounds__(256) void attnv_kernel(
    const float* __restrict__ attn, const float* __restrict__ kv,
    float* __restrict__ o)
{
    int bh = blockIdx.y;
    int b = bh / HH, h = bh % HH;
    int i0 = blockIdx.x * 64;
    __shared__ float As[32][68];   // As[j][i]
    __shared__ float Vs[32][64];   // Vs[j][d]
    int tid = threadIdx.x, tx = tid & 15, ty = tid >> 4;
    float acc[4][4] = {};

    const float* abase = attn + (size_t)bh * NN * NN;
    const float* vbase = kv + INNERD + h * DHD;   // V half of kv

    for (int j0 = 0; j0 < NN; j0 += 32) {
        #pragma unroll
        for (int v = 0; v < 2; v++) {            // A tile 64x32
            int lin = tid + v * 256;
            int r = lin >> 3, c = (lin & 7) * 4;
            float4 a = *(const float4*)&abase[(size_t)(i0 + r) * NN + j0 + c];
            As[c + 0][r] = a.x; As[c + 1][r] = a.y; As[c + 2][r] = a.z; As[c + 3][r] = a.w;
        }
        #pragma unroll
        for (int v = 0; v < 2; v++) {            // V tile 32x64
            int lin = tid + v * 256;
            int r = lin >> 4, c = (lin & 15) * 4;
            *(float4*)&Vs[r][c] =
                *(const float4*)&vbase[(size_t)(b * NN + j0 + r) * (2 * INNERD) + c];
        }
        __syncthreads();
        #pragma unroll
        for (int jj = 0; jj < 32; jj++) {
            float4 a4 = *(const float4*)&As[jj][ty * 4];
            float4 b4 = *(const float4*)&Vs[jj][tx * 4];
            float a[4] = {a4.x, a4.y, a4.z, a4.w};
            float bb[4] = {b4.x, b4.y, b4.z, b4.w};
            #pragma unroll
            for (int i = 0; i < 4; i++)
                #pragma unroll
                for (int j = 0; j < 4; j++)
                    acc[i][j] = fmaf(a[i], bb[j], acc[i][j]);
        }
        __syncthreads();
    }

    #pragma unroll
    for (int i = 0; i < 4; i++)
        #pragma unroll
        for (int j = 0; j < 4; j++)
            o[(size_t)(b * NN + i0 + ty * 4 + i) * INNERD + h * DHD + tx * 4 + j] = acc[i][j];
}

// ---------------------------------------------------------------------------
// Launch
// ---------------------------------------------------------------------------
extern "C" void kernel_launch(void* const* d_in, const int* in_sizes, int n_in,
                              void* d_out, int out_size)
{
    const float* x    = (const float*)d_in[0];
    const float* ln1g = (const float*)d_in[1];
    const float* ln1b = (const float*)d_in[2];
    const float* wq   = (const float*)d_in[3];
    const float* wkv  = (const float*)d_in[4];
    const float* scl  = (const float*)d_in[5];
    const float* mp   = (const float*)d_in[6];
    const float* mq   = (const float*)d_in[7];
    const float* wo   = (const float*)d_in[8];
    const float* bo   = (const float*)d_in[9];
    const float* ls1  = (const float*)d_in[10];
    const float* ln2g = (const float*)d_in[11];
    const float* ln2b = (const float*)d_in[12];
    const float* w1   = (const float*)d_in[13];
    const float* b1   = (const float*)d_in[14];
    const float* w2   = (const float*)d_in[15];
    const float* b2   = (const float*)d_in[16];
    const float* ls2  = (const float*)d_in[17];

    float *gx, *gy, *gq, *gkv, *go, *gh, *gdots, *gattn;
    cudaGetSymbolAddress((void**)&gx,    g_x);
    cudaGetSymbolAddress((void**)&gy,    g_y);
    cudaGetSymbolAddress((void**)&gq,    g_q);
    cudaGetSymbolAddress((void**)&gkv,   g_kv);
    cudaGetSymbolAddress((void**)&go,    g_o);
    cudaGetSymbolAddress((void**)&gh,    g_h);
    cudaGetSymbolAddress((void**)&gdots, g_dots);
    cudaGetSymbolAddress((void**)&gattn, g_attn);

    cudaMemcpyAsync(gx, x, (size_t)BN_ROWS * DIMD * sizeof(float),
                    cudaMemcpyDeviceToDevice, 0);

    for (int L = 0; L < DEPTH; L++) {
        const float* L_ln1g = ln1g + L * DIMD;
        const float* L_ln1b = ln1b + L * DIMD;
        const float* L_wq   = wq   + (size_t)L * DIMD * INNERD;
        const float* L_wkv  = wkv  + (size_t)L * DIMD * 2 * INNERD;
        const float* L_scl  = scl  + L * HH;
        const float* L_mp   = mp   + L * HH * HH;
        const float* L_mq   = mq   + L * HH * HH;
        const float* L_wo   = wo   + (size_t)L * INNERD * DIMD;
        const float* L_bo   = bo   + L * DIMD;
        const float* L_ls1  = ls1  + L * DIMD;
        const float* L_ln2g = ln2g + L * DIMD;
        const float* L_ln2b = ln2b + L * DIMD;
        const float* L_w1   = w1   + (size_t)L * DIMD * MLPD;
        const float* L_b1   = b1   + L * MLPD;
        const float* L_w2   = w2   + (size_t)L * MLPD * DIMD;
        const float* L_b2   = b2   + L * DIMD;
        const float* L_ls2  = ls2  + L * DIMD;

        // Attention
        ln_kernel<<<BN_ROWS, 128>>>(gx, L_ln1g, L_ln1b, gy);
        sgemm_kernel<0><<<dim3(INNERD / 64, BN_ROWS / 64), 256>>>(
            gy, L_wq, gq, BN_ROWS, DIMD, INNERD, nullptr, nullptr, nullptr);
        sgemm_kernel<0><<<dim3(2 * INNERD / 64, BN_ROWS / 64), 256>>>(
            gy, L_wkv, gkv, BN_ROWS, DIMD, 2 * INNERD, nullptr, nullptr, nullptr);
        dots_kernel<<<dim3(NN / 64, NN / 64, BB * HH), 256>>>(gq, gkv, L_scl, gdots);
        softmax_mix_kernel<<<BB * NN, 256>>>(gdots, L_mp, L_mq, gattn);
        attnv_kernel<<<dim3(NN / 64, BB * HH), 256>>>(gattn, gkv, go);
        sgemm_kernel<2><<<dim3(DIMD / 64, BN_ROWS / 64), 256>>>(
            go, L_wo, gx, BN_ROWS, INNERD, DIMD, L_bo, L_ls1, gx);

        // FFN
        ln_kernel<<<BN_ROWS, 128>>>(gx, L_ln2g, L_ln2b, gy);
        sgemm_kernel<1><<<dim3(MLPD / 64, BN_ROWS / 64), 256>>>(
            gy, L_w1, gh, BN_ROWS, DIMD, MLPD, L_b1, nullptr, nullptr);
        sgemm_kernel<2><<<dim3(DIMD / 64, BN_ROWS / 64), 256>>>(
            gh, L_w2, gx, BN_ROWS, MLPD, DIMD, L_b2, L_ls2, gx);
    }

    cudaMemcpyAsync(d_out, gx, (size_t)BN_ROWS * DIMD * sizeof(float),
                    cudaMemcpyDeviceToDevice, 0);
}

// round 7
// speedup vs baseline: 1.3854x; 1.3854x over previous
#include <cuda_runtime.h>
#include <cuda_bf16.h>
#include <math.h>
#include <stdint.h>

// Problem dims
#define BB   32
#define NN   256
#define DIMD 384
#define HH   6
#define DHD  64
#define MLPD 1536
#define DEPTH 12
#define INNERD 384
#define BN_ROWS (BB*NN)          // 8192
#define K3Q (3*DIMD)             // 1152
#define K3M (3*MLPD)             // 4608

// ---------------------------------------------------------------------------
// Device scratch
// ---------------------------------------------------------------------------
__device__ __align__(128) float g_x   [BN_ROWS*DIMD];
__device__ __align__(128) float g_qkv [BN_ROWS*K3Q];
__device__ __align__(128) float g_dots[BB*HH*NN*NN];
__device__ __align__(128) float g_attn[BB*HH*NN*NN];
__device__ __align__(128) __nv_bfloat16 g_yp[(size_t)BN_ROWS*K3Q];
__device__ __align__(128) __nv_bfloat16 g_op[(size_t)BN_ROWS*K3Q];
__device__ __align__(128) __nv_bfloat16 g_hp[(size_t)BN_ROWS*K3M];
__device__ __align__(128) __nv_bfloat16 g_wqkvp[(size_t)DEPTH*1152*K3Q];
__device__ __align__(128) __nv_bfloat16 g_wop  [(size_t)DEPTH*384 *K3Q];
__device__ __align__(128) __nv_bfloat16 g_w1p  [(size_t)DEPTH*1536*K3Q];
__device__ __align__(128) __nv_bfloat16 g_w2p  [(size_t)DEPTH*384 *K3M];

// ---------------------------------------------------------------------------
// Helpers
// ---------------------------------------------------------------------------
__device__ __forceinline__ uint32_t cvta_s(const void* p) {
    uint32_t a;
    asm("{ .reg .u64 t; cvta.to.shared.u64 t, %1; cvt.u32.u64 %0, t; }"
        : "=r"(a) : "l"(p));
    return a;
}
#define CP_ASYNC16(dst, src) \
    asm volatile("cp.async.cg.shared.global [%0], [%1], 16;" :: "r"(dst), "l"(src))
#define CP_COMMIT() asm volatile("cp.async.commit_group;")
#define CP_WAIT0()  asm volatile("cp.async.wait_group 0;" ::: "memory")

__device__ __forceinline__ void mma16816(float* d, const uint32_t* a, const uint32_t* b) {
    asm volatile(
        "mma.sync.aligned.m16n8k16.row.col.f32.bf16.bf16.f32 "
        "{%0,%1,%2,%3}, {%4,%5,%6,%7}, {%8,%9}, {%0,%1,%2,%3};\n"
        : "+f"(d[0]), "+f"(d[1]), "+f"(d[2]), "+f"(d[3])
        : "r"(a[0]), "r"(a[1]), "r"(a[2]), "r"(a[3]), "r"(b[0]), "r"(b[1]));
}

__device__ __forceinline__ void bf_split(float v, __nv_bfloat16& hi, __nv_bfloat16& lo) {
    hi = __float2bfloat16(v);
    lo = __float2bfloat16(v - __bfloat162float(hi));
}

// ---------------------------------------------------------------------------
// Weight transpose + split: W[K,N] fp32 -> rows n of [hi(K)|hi(K)|lo(K)]
// ---------------------------------------------------------------------------
__global__ __launch_bounds__(256) void wconv_kernel(
    const float* __restrict__ W, __nv_bfloat16* __restrict__ out,
    int K, int N, int rowStride, int rowOff)
{
    __shared__ float tile[32][33];
    int k0 = blockIdx.y * 32, n0 = blockIdx.x * 32;
    int tx = threadIdx.x & 31, ty = threadIdx.x >> 5;
    #pragma unroll
    for (int i = 0; i < 4; i++) {
        int r = ty + i * 8;
        tile[r][tx] = W[(size_t)(k0 + r) * N + n0 + tx];
    }
    __syncthreads();
    #pragma unroll
    for (int i = 0; i < 4; i++) {
        int r = ty + i * 8;
        float w = tile[tx][r];
        __nv_bfloat16 hi, lo; bf_split(w, hi, lo);
        __nv_bfloat16* o = out + (size_t)(rowOff + n0 + r) * rowStride + k0 + tx;
        o[0]     = hi;
        o[K]     = hi;
        o[2 * K] = lo;
    }
}

// ---------------------------------------------------------------------------
// LayerNorm with split-bf16 output: y'[m] = [hi(384)|lo(384)|hi(384)]
// ---------------------------------------------------------------------------
__global__ __launch_bounds__(128) void ln_split_kernel(
    const float* __restrict__ x, const float* __restrict__ g,
    const float* __restrict__ b, __nv_bfloat16* __restrict__ yp)
{
    int row = blockIdx.x;
    int t = threadIdx.x;
    const float* xr = x + (size_t)row * DIMD;
    float v0 = xr[t], v1 = xr[t + 128], v2 = xr[t + 256];

    __shared__ float scratch[4];
    float s = v0 + v1 + v2;
    #pragma unroll
    for (int o = 16; o; o >>= 1) s += __shfl_xor_sync(0xffffffffu, s, o);
    if ((t & 31) == 0) scratch[t >> 5] = s;
    __syncthreads();
    s = scratch[0] + scratch[1] + scratch[2] + scratch[3];
    float mean = s * (1.0f / DIMD);

    float d0 = v0 - mean, d1 = v1 - mean, d2 = v2 - mean;
    float q = d0 * d0 + d1 * d1 + d2 * d2;
    __syncthreads();
    #pragma unroll
    for (int o = 16; o; o >>= 1) q += __shfl_xor_sync(0xffffffffu, q, o);
    if ((t & 31) == 0) scratch[t >> 5] = q;
    __syncthreads();
    q = scratch[0] + scratch[1] + scratch[2] + scratch[3];
    float rstd = rsqrtf(q * (1.0f / DIMD) + 1e-5f);

    __nv_bfloat16* yr = yp + (size_t)row * K3Q;
    #pragma unroll
    for (int seg = 0; seg < 3; seg++) {
        int c = t + seg * 128;
        float d = (seg == 0 ? d0 : seg == 1 ? d1 : d2);
        float v = d * rstd * g[c] + b[c];
        __nv_bfloat16 hi, lo; bf_split(v, hi, lo);
        yr[c]            = hi;
        yr[DIMD + c]     = lo;
        yr[2 * DIMD + c] = hi;
    }
}

// ---------------------------------------------------------------------------
// HMMA split-bf16 GEMM: C[M,N] = A'[M,K3] x W'[N,K3]^T, fp32 accum.
// 128x128x32 CTA tile, 8 warps (64x32 each), cp.async double buffer.
// EPI 0: fp32 out. EPI 1: gelu(c+bias) -> split bf16. EPI 2: (c+bias)*ls+res.
// ---------------------------------------------------------------------------
#define GPITCH 40   // halves per smem row (20 words -> conflict-free frag loads)

template<int EPI>
__global__ __launch_bounds__(256) void tc_gemm(
    const __nv_bfloat16* __restrict__ A, const __nv_bfloat16* __restrict__ W,
    int K3, int N, int nchunks,
    float* __restrict__ Cf, __nv_bfloat16* __restrict__ Cs, int KsegOut,
    const float* __restrict__ bias, const float* __restrict__ ls,
    const float* __restrict__ res)
{
    __shared__ __nv_bfloat16 As[2][128 * GPITCH];
    __shared__ __nv_bfloat16 Bs[2][128 * GPITCH];

    int tid = threadIdx.x, lane = tid & 31, wid = tid >> 5;
    __builtin_assume(tid < 256);
    int wm = wid & 1, wn = wid >> 1;              // 2 (M) x 4 (N) warps
    int m0 = blockIdx.y * 128, n0 = blockIdx.x * 128;

    float acc[4][4][4] = {};

    // chunk loader: 128 rows x 32 halves for A and W each
    auto load_chunk = [&](int c, int buf) {
        int k0 = c * 32;
        #pragma unroll
        for (int rep = 0; rep < 2; rep++) {
            int u = tid + rep * 256;
            int row = u >> 2, q = u & 3;
            uint32_t da = cvta_s(&As[buf][row * GPITCH + q * 8]);
            uint32_t db = cvta_s(&Bs[buf][row * GPITCH + q * 8]);
            CP_ASYNC16(da, A + (size_t)(m0 + row) * K3 + k0 + q * 8);
            CP_ASYNC16(db, W + (size_t)(n0 + row) * K3 + k0 + q * 8);
        }
        CP_COMMIT();
    };

    load_chunk(0, 0);
    for (int c = 0; c < nchunks; c++) {
        CP_WAIT0();
        __syncthreads();
        if (c + 1 < nchunks) load_chunk(c + 1, (c + 1) & 1);

        const __nv_bfloat16* Ab = As[c & 1];
        const __nv_bfloat16* Bb = Bs[c & 1];
        #pragma unroll
        for (int kk = 0; kk < 32; kk += 16) {
            int kc = kk + (lane & 3) * 2;
            uint32_t af[4][4], bf[4][2];
            #pragma unroll
            for (int mi = 0; mi < 4; mi++) {
                int r = wm * 64 + mi * 16 + (lane >> 2);
                af[mi][0] = *(const uint32_t*)&Ab[r * GPITCH + kc];
                af[mi][1] = *(const uint32_t*)&Ab[(r + 8) * GPITCH + kc];
                af[mi][2] = *(const uint32_t*)&Ab[r * GPITCH + kc + 8];
                af[mi][3] = *(const uint32_t*)&Ab[(r + 8) * GPITCH + kc + 8];
            }
            #pragma unroll
            for (int ni = 0; ni < 4; ni++) {
                int n = wn * 32 + ni * 8 + (lane >> 2);
                bf[ni][0] = *(const uint32_t*)&Bb[n * GPITCH + kc];
                bf[ni][1] = *(const uint32_t*)&Bb[n * GPITCH + kc + 8];
            }
            #pragma unroll
            for (int mi = 0; mi < 4; mi++)
                #pragma unroll
                for (int ni = 0; ni < 4; ni++)
                    mma16816(acc[mi][ni], af[mi], bf[ni]);
        }
    }

    // Epilogue. d0,d1: row lane/4, cols 2*(lane%4)+{0,1}; d2,d3: row+8.
    #pragma unroll
    for (int mi = 0; mi < 4; mi++) {
        #pragma unroll
        for (int ni = 0; ni < 4; ni++) {
            int col = n0 + wn * 32 + ni * 8 + (lane & 3) * 2;
            #pragma unroll
            for (int hh = 0; hh < 2; hh++) {
                int m = m0 + wm * 64 + mi * 16 + (lane >> 2) + hh * 8;
                float v0 = acc[mi][ni][hh * 2 + 0];
                float v1 = acc[mi][ni][hh * 2 + 1];
                if (EPI == 0) {
                    Cf[(size_t)m * N + col]     = v0;
                    Cf[(size_t)m * N + col + 1] = v1;
                } else if (EPI == 1) {
                    #pragma unroll
                    for (int e = 0; e < 2; e++) {
                        float v = (e ? v1 : v0) + bias[col + e];
                        v = 0.5f * v * (1.0f + erff(v * 0.70710678118654752f));
                        __nv_bfloat16 hi, lo; bf_split(v, hi, lo);
                        __nv_bfloat16* o = Cs + (size_t)m * 3 * KsegOut + col + e;
                        o[0]           = hi;
                        o[KsegOut]     = lo;
                        o[2 * KsegOut] = hi;
                    }
                } else {
                    size_t i0 = (size_t)m * N + col;
                    Cf[i0]     = (v0 + bias[col])     * ls[col]     + res[i0];
                    Cf[i0 + 1] = (v1 + bias[col + 1]) * ls[col + 1] + res[i0 + 1];
                }
            }
        }
    }
}

// ---------------------------------------------------------------------------
// dots[b,h,i,j] = scale[h] * sum_d q[b,i,h,d]*k[b,j,h,d]  (fp32, fused qkv)
// ---------------------------------------------------------------------------
__global__ __launch_bounds__(256) void dots_kernel(
    const float* __restrict__ qkv, const float* __restrict__ scale,
    float* __restrict__ dots)
{
    int bh = blockIdx.z;
    int b = bh / HH, h = bh % HH;
    int i0 = blockIdx.y * 64, j0 = blockIdx.x * 64;
    __shared__ float Qs[64][65];
    __shared__ float Ks[64][65];
    int tid = threadIdx.x, tx = tid & 15, ty = tid >> 4;

    #pragma unroll
    for (int v = 0; v < 4; v++) {
        int lin = tid + v * 256;
        int r = lin >> 4, c = (lin & 15) * 4;
        float4 qa = *(const float4*)&qkv[(size_t)(b * NN + i0 + r) * K3Q + h * DHD + c];
        Qs[r][c] = qa.x; Qs[r][c + 1] = qa.y; Qs[r][c + 2] = qa.z; Qs[r][c + 3] = qa.w;
        float4 ka = *(const float4*)&qkv[(size_t)(b * NN + j0 + r) * K3Q + 384 + h * DHD + c];
        Ks[r][c] = ka.x; Ks[r][c + 1] = ka.y; Ks[r][c + 2] = ka.z; Ks[r][c + 3] = ka.w;
    }
    __syncthreads();

    float acc[4][4] = {};
    #pragma unroll 8
    for (int d = 0; d < 64; d++) {
        float a[4], bb[4];
        #pragma unroll
        for (int i = 0; i < 4; i++) a[i] = Qs[ty * 4 + i][d];
        #pragma unroll
        for (int j = 0; j < 4; j++) bb[j] = Ks[tx * 4 + j][d];
        #pragma unroll
        for (int i = 0; i < 4; i++)
            #pragma unroll
            for (int j = 0; j < 4; j++)
                acc[i][j] = fmaf(a[i], bb[j], acc[i][j]);
    }

    float sc = scale[h];
    #pragma unroll
    for (int i = 0; i < 4; i++)
        #pragma unroll
        for (int j = 0; j < 4; j++)
            dots[((size_t)bh * NN + i0 + ty * 4 + i) * NN + j0 + tx * 4 + j] = acc[i][j] * sc;
}

// ---------------------------------------------------------------------------
// Fused pre-mix -> diag mask -> softmax -> post-mix
// ---------------------------------------------------------------------------
__device__ __forceinline__ float block_reduce(float v, bool is_max, float* scratch)
{
    #pragma unroll
    for (int o = 16; o; o >>= 1) {
        float t = __shfl_xor_sync(0xffffffffu, v, o);
        v = is_max ? fmaxf(v, t) : v + t;
    }
    __syncthreads();
    if ((threadIdx.x & 31) == 0) scratch[threadIdx.x >> 5] = v;
    __syncthreads();
    float r = scratch[0];
    #pragma unroll
    for (int k = 1; k < 8; k++) r = is_max ? fmaxf(r, scratch[k]) : r + scratch[k];
    return r;
}

__global__ __launch_bounds__(256) void softmax_mix_kernel(
    const float* __restrict__ dots, const float* __restrict__ mp,
    const float* __restrict__ mq, float* __restrict__ attn)
{
    int b = blockIdx.x >> 8;
    int i = blockIdx.x & 255;
    int j = threadIdx.x;

    __shared__ float smp[36], smq[36], red[8];
    if (j < 36) { smp[j] = mp[j]; smq[j] = mq[j]; }

    float raw[HH];
    #pragma unroll
    for (int h = 0; h < HH; h++)
        raw[h] = dots[(((size_t)b * HH + h) * NN + i) * NN + j];
    __syncthreads();

    float pm[HH];
    #pragma unroll
    for (int g = 0; g < HH; g++) {
        float s = 0.0f;
        #pragma unroll
        for (int h = 0; h < HH; h++) s = fmaf(raw[h], smp[h * HH + g], s);
        pm[g] = s;
    }
    if (j == i) {
        #pragma unroll
        for (int g = 0; g < HH; g++) pm[g] = -INFINITY;
    }

    float a[HH];
    #pragma unroll
    for (int g = 0; g < HH; g++) {
        float m  = block_reduce(pm[g], true, red);
        float e  = expf(pm[g] - m);
        float s  = block_reduce(e, false, red);
        a[g] = e / s;
    }

    #pragma unroll
    for (int g = 0; g < HH; g++) {
        float s = 0.0f;
        #pragma unroll
        for (int h = 0; h < HH; h++) s = fmaf(a[h], smq[h * HH + g], s);
        attn[(((size_t)b * HH + g) * NN + i) * NN + j] = s;
    }
}

// ---------------------------------------------------------------------------
// o'[b,i,:] split-bf16 = sum_j attn[b,h,i,j] * v[b,j,h,d]
// ---------------------------------------------------------------------------
__global__ __launch_bounds__(256) void attnv_kernel(
    const float* __restrict__ attn, const float* __restrict__ qkv,
    __nv_bfloat16* __restrict__ op)
{
    int bh = blockIdx.y;
    int b = bh / HH, h = bh % HH;
    int i0 = blockIdx.x * 64;
    __shared__ float As[32][68];
    __shared__ float Vs[32][64];
    int tid = threadIdx.x, tx = tid & 15, ty = tid >> 4;
    float acc[4][4] = {};

    const float* abase = attn + (size_t)bh * NN * NN;
    const float* vbase = qkv + 768 + h * DHD;

    for (int j0 = 0; j0 < NN; j0 += 32) {
        #pragma unroll
        for (int v = 0; v < 2; v++) {
            int lin = tid + v * 256;
            int r = lin >> 3, c = (lin & 7) * 4;
            float4 a = *(const float4*)&abase[(size_t)(i0 + r) * NN + j0 + c];
            As[c + 0][r] = a.x; As[c + 1][r] = a.y; As[c + 2][r] = a.z; As[c + 3][r] = a.w;
        }
        #pragma unroll
        for (int v = 0; v < 2; v++) {
            int lin = tid + v * 256;
            int r = lin >> 4, c = (lin & 15) * 4;
            *(float4*)&Vs[r][c] =
                *(const float4*)&vbase[(size_t)(b * NN + j0 + r) * K3Q + c];
        }
        __syncthreads();
        #pragma unroll
        for (int jj = 0; jj < 32; jj++) {
            float4 a4 = *(const float4*)&As[jj][ty * 4];
            float4 b4 = *(const float4*)&Vs[jj][tx * 4];
            float a[4] = {a4.x, a4.y, a4.z, a4.w};
            float bb[4] = {b4.x, b4.y, b4.z, b4.w};
            #pragma unroll
            for (int i = 0; i < 4; i++)
                #pragma unroll
                for (int j = 0; j < 4; j++)
                    acc[i][j] = fmaf(a[i], bb[j], acc[i][j]);
        }
        __syncthreads();
    }

    #pragma unroll
    for (int i = 0; i < 4; i++) {
        size_t row = (size_t)(b * NN + i0 + ty * 4 + i);
        #pragma unroll
        for (int j = 0; j < 4; j++) {
            int col = h * DHD + tx * 4 + j;
            __nv_bfloat16 hi, lo; bf_split(acc[i][j], hi, lo);
            __nv_bfloat16* o = op + row * K3Q + col;
            o[0]          = hi;
            o[INNERD]     = lo;
            o[2 * INNERD] = hi;
        }
    }
}

// ---------------------------------------------------------------------------
// Launch
// ---------------------------------------------------------------------------
extern "C" void kernel_launch(void* const* d_in, const int* in_sizes, int n_in,
                              void* d_out, int out_size)
{
    const float* x    = (const float*)d_in[0];
    const float* ln1g = (const float*)d_in[1];
    const float* ln1b = (const float*)d_in[2];
    const float* wq   = (const float*)d_in[3];
    const float* wkv  = (const float*)d_in[4];
    const float* scl  = (const float*)d_in[5];
    const float* mp   = (const float*)d_in[6];
    const float* mq   = (const float*)d_in[7];
    const float* wo   = (const float*)d_in[8];
    const float* bo   = (const float*)d_in[9];
    const float* ls1  = (const float*)d_in[10];
    const float* ln2g = (const float*)d_in[11];
    const float* ln2b = (const float*)d_in[12];
    const float* w1   = (const float*)d_in[13];
    const float* b1   = (const float*)d_in[14];
    const float* w2   = (const float*)d_in[15];
    const float* b2   = (const float*)d_in[16];
    const float* ls2  = (const float*)d_in[17];

    float *gx, *gqkv, *gdots, *gattn;
    __nv_bfloat16 *gyp, *gop, *ghp, *gwqkvp, *gwop, *gw1p, *gw2p;
    cudaGetSymbolAddress((void**)&gx,     g_x);
    cudaGetSymbolAddress((void**)&gqkv,   g_qkv);
    cudaGetSymbolAddress((void**)&gdots,  g_dots);
    cudaGetSymbolAddress((void**)&gattn,  g_attn);
    cudaGetSymbolAddress((void**)&gyp,    g_yp);
    cudaGetSymbolAddress((void**)&gop,    g_op);
    cudaGetSymbolAddress((void**)&ghp,    g_hp);
    cudaGetSymbolAddress((void**)&gwqkvp, g_wqkvp);
    cudaGetSymbolAddress((void**)&gwop,   g_wop);
    cudaGetSymbolAddress((void**)&gw1p,   g_w1p);
    cudaGetSymbolAddress((void**)&gw2p,   g_w2p);

    cudaMemcpyAsync(gx, x, (size_t)BN_ROWS * DIMD * sizeof(float),
                    cudaMemcpyDeviceToDevice, 0);

    // Weight conversion (transpose + bf16 split)
    for (int L = 0; L < DEPTH; L++) {
        wconv_kernel<<<dim3(384/32, 384/32), 256>>>(
            wq  + (size_t)L*DIMD*INNERD,   gwqkvp + (size_t)L*1152*K3Q, 384, 384,  K3Q, 0);
        wconv_kernel<<<dim3(768/32, 384/32), 256>>>(
            wkv + (size_t)L*DIMD*2*INNERD, gwqkvp + (size_t)L*1152*K3Q, 384, 768,  K3Q, 384);
        wconv_kernel<<<dim3(384/32, 384/32), 256>>>(
            wo  + (size_t)L*INNERD*DIMD,   gwop   + (size_t)L*384*K3Q,  384, 384,  K3Q, 0);
        wconv_kernel<<<dim3(1536/32, 384/32), 256>>>(
            w1  + (size_t)L*DIMD*MLPD,     gw1p   + (size_t)L*1536*K3Q, 384, 1536, K3Q, 0);
        wconv_kernel<<<dim3(384/32, 1536/32), 256>>>(
            w2  + (size_t)L*MLPD*DIMD,     gw2p   + (size_t)L*384*K3M,  1536, 384, K3M, 0);
    }

    for (int L = 0; L < DEPTH; L++) {
        const __nv_bfloat16* L_wqkvp = gwqkvp + (size_t)L*1152*K3Q;
        const __nv_bfloat16* L_wop   = gwop   + (size_t)L*384*K3Q;
        const __nv_bfloat16* L_w1p   = gw1p   + (size_t)L*1536*K3Q;
        const __nv_bfloat16* L_w2p   = gw2p   + (size_t)L*384*K3M;

        // Attention
        ln_split_kernel<<<BN_ROWS, 128>>>(gx, ln1g + L*DIMD, ln1b + L*DIMD, gyp);
        tc_gemm<0><<<dim3(1152/128, BN_ROWS/128), 256>>>(
            gyp, L_wqkvp, K3Q, 1152, K3Q/32, gqkv, nullptr, 0,
            nullptr, nullptr, nullptr);
        dots_kernel<<<dim3(NN/64, NN/64, BB*HH), 256>>>(gqkv, scl + L*HH, gdots);
        softmax_mix_kernel<<<BB*NN, 256>>>(gdots, mp + L*HH*HH, mq + L*HH*HH, gattn);
        attnv_kernel<<<dim3(NN/64, BB*HH), 256>>>(gattn, gqkv, gop);
        tc_gemm<2><<<dim3(384/128, BN_ROWS/128), 256>>>(
            gop, L_wop, K3Q, 384, K3Q/32, gx, nullptr, 0,
            bo + L*DIMD, ls1 + L*DIMD, gx);

        // FFN
        ln_split_kernel<<<BN_ROWS, 128>>>(gx, ln2g + L*DIMD, ln2b + L*DIMD, gyp);
        tc_gemm<1><<<dim3(1536/128, BN_ROWS/128), 256>>>(
            gyp, L_w1p, K3Q, 1536, K3Q/32, nullptr, ghp, MLPD,
            b1 + L*MLPD, nullptr, nullptr);
        tc_gemm<2><<<dim3(384/128, BN_ROWS/128), 256>>>(
            ghp, L_w2p, K3M, 384, K3M/32, gx, nullptr, 0,
            b2 + L*DIMD, ls2 + L*DIMD, gx);
    }

    cudaMemcpyAsync(d_out, gx, (size_t)BN_ROWS * DIMD * sizeof(float),
                    cudaMemcpyDeviceToDevice, 0);
}